// round 1
// baseline (speedup 1.0000x reference)
#include <cuda_runtime.h>
#include <cstdint>
#include <cstddef>

#define NN   25000
#define EE   50000
#define EE3  40000
#define DIM  64

// ---------------- scratch (device globals; no allocation at launch time) ----
__device__ float g_h[NN * DIM];                     // node features / GRU state
__device__ float g_agg[NN * DIM];                   // scatter-sum accumulator
__device__ float g_hr[EE * 128];                    // edge hidden (relu(ea@W_e1))
__device__ float g_Wedge[(size_t)EE * DIM * DIM];   // 819 MB per-edge weight mats
__device__ float g_cnt[NN];
__device__ float g_invcnt[NN];

// ---------------- f32x2 helpers ---------------------------------------------
__device__ __forceinline__ unsigned long long fma2(unsigned long long a,
                                                   unsigned long long b,
                                                   unsigned long long c) {
    unsigned long long d;
    asm("fma.rn.f32x2 %0, %1, %2, %3;" : "=l"(d) : "l"(a), "l"(b), "l"(c));
    return d;
}
__device__ __forceinline__ unsigned long long dup2(float x) {
    unsigned long long d;
    asm("mov.b64 %0, {%1, %1};" : "=l"(d) : "f"(x));
    return d;
}
__device__ __forceinline__ float2 unpack2(unsigned long long v) {
    float2 r;
    asm("mov.b64 {%0, %1}, %2;" : "=f"(r.x), "=f"(r.y) : "l"(v));
    return r;
}

// ---------------- small kernels ----------------------------------------------
__global__ void zero_agg_kernel(int n) {
    int i = blockIdx.x * 256 + threadIdx.x;
    if (i < n) g_agg[i] = 0.f;
}
__global__ void zero_cnt_kernel(int n) {
    int i = blockIdx.x * 256 + threadIdx.x;
    if (i < n) g_cnt[i] = 0.f;
}
__global__ void count_kernel(const int* __restrict__ dst, int E) {
    int e = blockIdx.x * 256 + threadIdx.x;
    if (e < E) atomicAdd(&g_cnt[dst[e]], 1.f);
}
__global__ void invcnt_kernel(int N) {
    int i = blockIdx.x * 256 + threadIdx.x;
    if (i < N) g_invcnt[i] = 1.f / fmaxf(g_cnt[i], 1.f);
}

// out = relu(x @ W_node + b_node)   [N,8]x[8,64]
__global__ void node_mlp_kernel(const float* __restrict__ x,
                                const float* __restrict__ Wn,
                                const float* __restrict__ bn, int N) {
    int i = blockIdx.x * 256 + threadIdx.x;
    if (i >= N * DIM) return;
    int n = i >> 6, f = i & 63;
    float acc = bn[f];
#pragma unroll
    for (int k = 0; k < 8; k++) acc += x[n * 8 + k] * Wn[k * DIM + f];
    g_h[i] = fmaxf(acc, 0.f);
}

// per-edge: ea = relu(edge_attr@W_ea+b_ea) [19->12]; hr = relu(ea@W_e1+b_e1) [12->128]
__global__ void __launch_bounds__(128) edge_mlp_kernel(
    const float* __restrict__ ea_in, const float* __restrict__ W_ea,
    const float* __restrict__ b_ea, const float* __restrict__ W_e1,
    const float* __restrict__ b_e1, int E) {
    __shared__ float row[19];
    __shared__ float eah[12];
    int e = blockIdx.x;
    int tid = threadIdx.x;
    if (tid < 19) row[tid] = ea_in[(size_t)e * 19 + tid];
    __syncthreads();
    if (tid < 12) {
        float a = b_ea[tid];
#pragma unroll
        for (int i = 0; i < 19; i++) a += row[i] * W_ea[i * 12 + tid];
        eah[tid] = fmaxf(a, 0.f);
    }
    __syncthreads();
    float a = b_e1[tid];
#pragma unroll
    for (int k = 0; k < 12; k++) a += eah[k] * W_e1[k * 128 + tid];
    g_hr[(size_t)e * 128 + tid] = fmaxf(a, 0.f);
}

// Wedge[E,4096] = hr[E,128] @ W_e2[128,4096] + b_e2
// tile: 32 edges x 128 cols per 256-thread block, f32x2 accumulators.
__global__ void __launch_bounds__(256) wedge_gemm_kernel(
    const float* __restrict__ W2, const float* __restrict__ b2, int E) {
    __shared__ float hrT[128][32];   // hr tile transposed: [k][edge]
    int ebase = blockIdx.x * 32;
    int colbase = blockIdx.y * 128;
    int tid = threadIdx.x;
    for (int i = tid; i < 32 * 128; i += 256) {
        int e = i >> 7, k = i & 127;
        hrT[k][e] = (ebase + e < E) ? g_hr[(size_t)(ebase + e) * 128 + k] : 0.f;
    }
    __syncthreads();
    int tx = tid & 31;   // col group: 4 consecutive cols
    int ty = tid >> 5;   // edge group: 4 consecutive edges
    unsigned long long acc[4][2];
#pragma unroll
    for (int i = 0; i < 4; i++) { acc[i][0] = 0ull; acc[i][1] = 0ull; }
    const float* Wp = W2 + (size_t)colbase + tx * 4;
#pragma unroll 8
    for (int k = 0; k < 128; k++) {
        float4 a4 = *(const float4*)&hrT[k][ty * 4];
        ulonglong2 bv = *reinterpret_cast<const ulonglong2*>(Wp + (size_t)k * 4096);
        unsigned long long a0 = dup2(a4.x), a1 = dup2(a4.y),
                           a2 = dup2(a4.z), a3 = dup2(a4.w);
        acc[0][0] = fma2(a0, bv.x, acc[0][0]); acc[0][1] = fma2(a0, bv.y, acc[0][1]);
        acc[1][0] = fma2(a1, bv.x, acc[1][0]); acc[1][1] = fma2(a1, bv.y, acc[1][1]);
        acc[2][0] = fma2(a2, bv.x, acc[2][0]); acc[2][1] = fma2(a2, bv.y, acc[2][1]);
        acc[3][0] = fma2(a3, bv.x, acc[3][0]); acc[3][1] = fma2(a3, bv.y, acc[3][1]);
    }
    float4 bias = *(const float4*)&b2[colbase + tx * 4];
#pragma unroll
    for (int i = 0; i < 4; i++) {
        int e = ebase + ty * 4 + i;
        if (e < E) {
            float2 lo = unpack2(acc[i][0]);
            float2 hi = unpack2(acc[i][1]);
            float4 v = make_float4(lo.x + bias.x, lo.y + bias.y,
                                   hi.x + bias.z, hi.y + bias.w);
            *(float4*)&g_Wedge[(size_t)e * 4096 + colbase + tx * 4] = v;
        }
    }
}

// msg[e] = h[src[e]] @ Wedge[e]; atomically scattered to g_agg[dst[e]].
// 16 edges per 256-thread block; 16 threads per edge, 4 cols each (float4 reads).
__global__ void __launch_bounds__(256) msg_scatter_kernel(
    const int* __restrict__ src, const int* __restrict__ dst, int E) {
    __shared__ float outs[16][64];
    int ty = threadIdx.x >> 4;   // edge slot
    int tx = threadIdx.x & 15;   // col group
    int e = blockIdx.x * 16 + ty;
    if (e < E) {
        int s = src[e];
        *(float4*)&outs[ty][tx * 4] = *(const float4*)&g_h[(size_t)s * 64 + tx * 4];
    }
    __syncthreads();
    if (e >= E) return;
    float a0 = 0.f, a1 = 0.f, a2 = 0.f, a3 = 0.f;
    const float4* Wp = (const float4*)(g_Wedge + (size_t)e * 4096) + tx;
#pragma unroll 4
    for (int d = 0; d < 64; d++) {
        float a = outs[ty][d];
        float4 w = Wp[d * 16];
        a0 += a * w.x; a1 += a * w.y; a2 += a * w.z; a3 += a * w.w;
    }
    int dn = dst[e];
    float* ap = g_agg + (size_t)dn * 64 + tx * 4;
    atomicAdd(ap + 0, a0);
    atomicAdd(ap + 1, a1);
    atomicAdd(ap + 2, a2);
    atomicAdd(ap + 3, a3);
}

// GRU update, 32 nodes per block; W_ih/W_hh staged in padded dynamic shared.
#define GRU_NODES 32
#define GRU_SMEM_FLOATS (2 * 192 * 65 + 2 * GRU_NODES * 64)
__global__ void __launch_bounds__(256) gru_kernel(
    const float* __restrict__ conv_bias,
    const float* __restrict__ W_ih, const float* __restrict__ b_ih,
    const float* __restrict__ W_hh, const float* __restrict__ b_hh, int N) {
    extern __shared__ float sm[];
    float* wih = sm;                     // [192][65] padded
    float* whh = sm + 192 * 65;
    float* ms  = whh + 192 * 65;         // [32][64]
    float* hs  = ms + GRU_NODES * 64;    // [32][64]
    int tid = threadIdx.x;
    for (int i = tid; i < 192 * 64; i += 256) {
        int j = i >> 6, k = i & 63;
        wih[j * 65 + k] = W_ih[i];
        whh[j * 65 + k] = W_hh[i];
    }
    int nb = blockIdx.x * GRU_NODES;
    for (int i = tid; i < GRU_NODES * 64; i += 256) {
        int nl = i >> 6, f = i & 63;
        int n = nb + nl;
        if (n < N) {
            ms[nl * 64 + f] =
                fmaxf(g_agg[(size_t)n * 64 + f] * g_invcnt[n] + conv_bias[f], 0.f);
            hs[nl * 64 + f] = g_h[(size_t)n * 64 + f];
        }
    }
    __syncthreads();
    int lane = tid & 63;   // feature f
    int grp = tid >> 6;    // 0..3
    float bir = b_ih[lane], biz = b_ih[64 + lane], bin = b_ih[128 + lane];
    float bhr = b_hh[lane], bhz = b_hh[64 + lane], bhn = b_hh[128 + lane];
    for (int nl = grp; nl < GRU_NODES; nl += 4) {
        int n = nb + nl;
        if (n >= N) continue;
        float ir = bir, iz = biz, inn = bin;
        float hrr = bhr, hz = bhz, hn = bhn;
#pragma unroll 8
        for (int k = 0; k < 64; k++) {
            float mk = ms[nl * 64 + k], hk = hs[nl * 64 + k];
            ir  += mk * wih[lane * 65 + k];
            iz  += mk * wih[(64 + lane) * 65 + k];
            inn += mk * wih[(128 + lane) * 65 + k];
            hrr += hk * whh[lane * 65 + k];
            hz  += hk * whh[(64 + lane) * 65 + k];
            hn  += hk * whh[(128 + lane) * 65 + k];
        }
        float r = 1.f / (1.f + __expf(-(ir + hrr)));
        float z = 1.f / (1.f + __expf(-(iz + hz)));
        float ng = tanhf(inn + r * hn);
        g_h[(size_t)n * 64 + lane] = (1.f - z) * ng + z * hs[nl * 64 + lane];
    }
}

// final: feat=[0.5*(h[a]+h[b]) (64) | edge_attr3 (8)]; y = relu(feat@W_l1+b_l1)@W_l2+b_l2
#define FIN_PER_BLOCK 32
__global__ void __launch_bounds__(128) final_mlp_kernel(
    const float* __restrict__ ea3, const int* __restrict__ idx_a,
    const int* __restrict__ idx_b, const float* __restrict__ W_l1,
    const float* __restrict__ b_l1, const float* __restrict__ W_l2,
    const float* __restrict__ b_l2, float* __restrict__ out, int E3) {
    __shared__ float wl1[72 * 128];
    __shared__ float wl2[128];
    __shared__ float feat[72];
    __shared__ float red[4];
    int tid = threadIdx.x;
    for (int i = tid; i < 72 * 128; i += 128) wl1[i] = W_l1[i];
    wl2[tid] = W_l2[tid];
    float bl1 = b_l1[tid];
    int base = blockIdx.x * FIN_PER_BLOCK;
    for (int t = 0; t < FIN_PER_BLOCK; t++) {
        int e = base + t;
        if (e >= E3) break;
        __syncthreads();   // protects feat/red reuse + first-iter staging
        if (tid < 64) {
            int a = idx_a[e], b = idx_b[e];
            feat[tid] = 0.5f * (g_h[(size_t)a * 64 + tid] + g_h[(size_t)b * 64 + tid]);
        } else if (tid < 72) {
            feat[tid] = ea3[(size_t)e * 8 + (tid - 64)];
        }
        __syncthreads();
        float acc = bl1;
#pragma unroll
        for (int i = 0; i < 72; i++) acc += feat[i] * wl1[i * 128 + tid];
        acc = fmaxf(acc, 0.f) * wl2[tid];
#pragma unroll
        for (int o = 16; o > 0; o >>= 1) acc += __shfl_down_sync(0xffffffffu, acc, o);
        if ((tid & 31) == 0) red[tid >> 5] = acc;
        __syncthreads();
        if (tid == 0) out[e] = red[0] + red[1] + red[2] + red[3] + b_l2[0];
    }
}

// ---------------- launch ------------------------------------------------------
extern "C" void kernel_launch(void* const* d_in, const int* in_sizes, int n_in,
                              void* d_out, int out_size) {
    const float* x          = (const float*)d_in[0];
    const float* edge_attr  = (const float*)d_in[1];
    const float* edge_attr3 = (const float*)d_in[2];
    const int*   edge_index  = (const int*)d_in[3];
    const int*   edge_index3 = (const int*)d_in[4];
    const float* W_node = (const float*)d_in[5];
    const float* b_node = (const float*)d_in[6];
    const float* W_ea   = (const float*)d_in[7];
    const float* b_ea   = (const float*)d_in[8];
    const float* W_e1   = (const float*)d_in[9];
    const float* b_e1   = (const float*)d_in[10];
    const float* W_e2   = (const float*)d_in[11];
    const float* b_e2   = (const float*)d_in[12];
    const float* conv_bias = (const float*)d_in[13];
    const float* W_ih = (const float*)d_in[14];
    const float* b_ih = (const float*)d_in[15];
    const float* W_hh = (const float*)d_in[16];
    const float* b_hh = (const float*)d_in[17];
    const float* W_l1 = (const float*)d_in[18];
    const float* b_l1 = (const float*)d_in[19];
    const float* W_l2 = (const float*)d_in[20];
    const float* b_l2 = (const float*)d_in[21];

    int N  = in_sizes[0] / 8;
    int E  = in_sizes[1] / 19;
    int E3 = in_sizes[2] / 8;
    const int* src  = edge_index;
    const int* dst  = edge_index + E;
    const int* e3a  = edge_index3;
    const int* e3b  = edge_index3 + E3;
    float* out = (float*)d_out;

    cudaFuncSetAttribute(gru_kernel, cudaFuncAttributeMaxDynamicSharedMemorySize,
                         GRU_SMEM_FLOATS * (int)sizeof(float));

    // 1. node MLP
    node_mlp_kernel<<<(N * DIM + 255) / 256, 256>>>(x, W_node, b_node, N);
    // 2. edge MLP -> hr
    edge_mlp_kernel<<<E, 128>>>(edge_attr, W_ea, b_ea, W_e1, b_e1, E);
    // 3. big GEMM -> Wedge
    {
        dim3 grid((E + 31) / 32, 32);
        wedge_gemm_kernel<<<grid, 256>>>(W_e2, b_e2, E);
    }
    // 4. degree counts
    zero_cnt_kernel<<<(N + 255) / 256, 256>>>(N);
    count_kernel<<<(E + 255) / 256, 256>>>(dst, E);
    invcnt_kernel<<<(N + 255) / 256, 256>>>(N);
    // 5. three conv + GRU iterations
    for (int it = 0; it < 3; it++) {
        zero_agg_kernel<<<(N * DIM + 255) / 256, 256>>>(N * DIM);
        msg_scatter_kernel<<<(E + 15) / 16, 256>>>(src, dst, E);
        gru_kernel<<<(N + GRU_NODES - 1) / GRU_NODES, 256,
                     GRU_SMEM_FLOATS * (int)sizeof(float)>>>(
            conv_bias, W_ih, b_ih, W_hh, b_hh, N);
    }
    // 6. final pair MLP
    final_mlp_kernel<<<(E3 + FIN_PER_BLOCK - 1) / FIN_PER_BLOCK, 128>>>(
        edge_attr3, e3a, e3b, W_l1, b_l1, W_l2, b_l2, out, E3);
}